// round 14
// baseline (speedup 1.0000x reference)
#include <cuda_runtime.h>
#include <cuda_bf16.h>
#include <cstdint>

#define BB 128
#define TT 1024
#define EE 512
#define HH 1024
#define VV 512
#define NB 224
#define NT 128
#define BH (BB*HH)
#define BTV ((size_t)BB*TT*VV)

// smem: persistent B 64KB (4 chunks x 16KB) + single A buffer 32KB
#define BCH    16384           // B chunk: 2 terms x 64 rows x 128B
#define AB0    65536
#define ABSZ   32768           // A chunk: 2 terms x 128 rows x 128B
#define DYNB_ALLOC (AB0 + ABSZ + 1024)

__device__ __align__(16) float g_tokproj[VV * HH];
__device__ __align__(16) float g_P0p[4][BH];
__device__ __align__(16) float g_P1p[8][BH];            // P1a 0-3, P1b 4-7
__device__ __align__(16) float g_Py[4][BB * VV];
__device__ __align__(16) __nv_bfloat16 g_h0sp[2][BH];
__device__ __align__(16) __nv_bfloat16 g_h1sp[2][BH];
__device__ __align__(16) __nv_bfloat16 g_w0sp[2][HH * HH];
__device__ __align__(16) __nv_bfloat16 g_w1sp[2][HH * HH];
__device__ __align__(16) __nv_bfloat16 g_w2sp[2][HH * HH];
__device__ __align__(16) __nv_bfloat16 g_wysp[2][VV * HH];
__device__ unsigned long long g_br[8];
__device__ unsigned long long g_ep[NB];

__device__ __forceinline__ uint32_t smem_u32(const void* p) {
    uint32_t a;
    asm("{ .reg .u64 t; cvta.to.shared.u64 t, %1; cvt.u32.u64 %0, t; }" : "=r"(a) : "l"(p));
    return a;
}
__device__ __forceinline__ void cp16(uint32_t dst, const void* src) {
    asm volatile("cp.async.cg.shared.global [%0], [%1], 16;" :: "r"(dst), "l"(src) : "memory");
}
#define CP_COMMIT() asm volatile("cp.async.commit_group;" ::: "memory")
#define CP_WAIT0()  asm volatile("cp.async.wait_group 0;" ::: "memory")
#define STS128(a, x, y, z, w) \
    asm volatile("st.shared.v4.b32 [%0], {%1,%2,%3,%4};" \
                 :: "r"(a), "r"(x), "r"(y), "r"(z), "r"(w) : "memory")
#define LDSM4(r, a) \
    asm volatile("ldmatrix.sync.aligned.m8n8.x4.shared.b16 {%0,%1,%2,%3}, [%4];" \
        : "=r"((r)[0]), "=r"((r)[1]), "=r"((r)[2]), "=r"((r)[3]) : "r"(a))
#define MMA16816(c, a, b0r, b1r) \
    asm volatile("mma.sync.aligned.m16n8k16.row.col.f32.bf16.bf16.f32 " \
        "{%0,%1,%2,%3}, {%4,%5,%6,%7}, {%8,%9}, {%0,%1,%2,%3};" \
        : "+f"((c)[0]), "+f"((c)[1]), "+f"((c)[2]), "+f"((c)[3]) \
        : "r"((a)[0]), "r"((a)[1]), "r"((a)[2]), "r"((a)[3]), "r"(b0r), "r"(b1r))

__device__ __forceinline__ void grid_bar(unsigned long long& ep) {
    ep += (unsigned long long)NB;
    __syncthreads();
    if (threadIdx.x == 0) {
        __threadfence();
        atomicAdd(&g_br[blockIdx.x & 7], 1ULL);
        for (;;) {
            unsigned long long s = 0;
#pragma unroll
            for (int i = 0; i < 8; i++) s += *(volatile unsigned long long*)&g_br[i];
            if (s >= ep) break;
            __nanosleep(32);
        }
        __threadfence();
    }
    __syncthreads();
}

__device__ __forceinline__ void split2(float x, __nv_bfloat16& d0, __nv_bfloat16& d1) {
    __nv_bfloat16 b0 = __float2bfloat16(x);
    d0 = b0;
    d1 = __float2bfloat16(x - __bfloat162float(b0));
}
__device__ __forceinline__ void st_split4(__nv_bfloat16* d0, __nv_bfloat16* d1,
                                          size_t idx, float4 v) {
    __nv_bfloat16 a0, b0, a1, b1, a2, b2, a3, b3;
    split2(v.x, a0, b0); split2(v.y, a1, b1);
    split2(v.z, a2, b2); split2(v.w, a3, b3);
    __nv_bfloat162 lo0(a0, a1), hi0(a2, a3), lo1(b0, b1), hi1(b2, b3);
    *(uint2*)(d0 + idx) = make_uint2(*(uint32_t*)&lo0, *(uint32_t*)&hi0);
    *(uint2*)(d1 + idx) = make_uint2(*(uint32_t*)&lo1, *(uint32_t*)&hi1);
}

// SIMT fp32 64x64 GEMM (tokproj prologue only, NT=128)
template <typename LA, typename LB, typename ST>
__device__ __forceinline__ void gemm64(float* sA, float* sB, int kend, LA la, LB lb, ST st) {
    const int tid = threadIdx.x;
    const int tx = tid & 15, ty = tid >> 4;      // ty 0..7, 8 rows each
    float acc[8][4];
#pragma unroll
    for (int i = 0; i < 8; i++)
#pragma unroll
        for (int j = 0; j < 4; j++) acc[i][j] = 0.f;
    for (int k0 = 0; k0 < kend; k0 += 32) {
#pragma unroll
        for (int i = 0; i < 16; i++) {
            int idx = tid + i * NT;
            int k = idx & 31, r = idx >> 5;
            sA[k * 68 + r] = la(r, k0 + k);
            sB[k * 68 + r] = lb(r, k0 + k);
        }
        __syncthreads();
#pragma unroll
        for (int kk = 0; kk < 32; kk++) {
            float4 a0 = *(const float4*)(sA + kk * 68 + 8 * ty);
            float4 a1 = *(const float4*)(sA + kk * 68 + 8 * ty + 4);
            float4 b = *(const float4*)(sB + kk * 68 + 4 * tx);
            float av[8] = {a0.x, a0.y, a0.z, a0.w, a1.x, a1.y, a1.z, a1.w};
            float bv[4] = {b.x, b.y, b.z, b.w};
#pragma unroll
            for (int i = 0; i < 8; i++)
#pragma unroll
                for (int j = 0; j < 4; j++) acc[i][j] = fmaf(av[i], bv[j], acc[i][j]);
        }
        __syncthreads();
    }
#pragma unroll
    for (int i = 0; i < 8; i++)
        st(8 * ty + i, 4 * tx, make_float4(acc[i][0], acc[i][1], acc[i][2], acc[i][3]));
}

// stage one A chunk (32KB): 2 terms x 128 rows x 64 K-cols
__device__ __forceinline__ void stage_a(uint32_t ab, const __nv_bfloat16* A0,
                                        const __nv_bfloat16* A1, int kg) {
    const int tid = threadIdx.x;
#pragma unroll
    for (int it = 0; it < 16; it++) {
        int id = tid + it * NT;                        // 0..2047
        int i = id >> 10, rem = id & 1023, r = rem >> 3, seg = rem & 7;
        const __nv_bfloat16* s = (i ? A1 : A0) + (size_t)r * HH + kg + seg * 8;
        cp16(ab + i * 16384 + r * 128 + ((seg ^ (r & 7)) << 4), s);
    }
    CP_COMMIT();
}

// K=64 chunk, job 128x64: 4 warps = 2M(64) x 2N(32), 3 products
__device__ __forceinline__ void chunk_mma(float acc[4][4][4], uint32_t ab, uint32_t pb,
                                          int wm, int wn, int lane) {
#pragma unroll
    for (int kk = 0; kk < 4; kk++) {
        uint32_t af[2][4][4];
#pragma unroll
        for (int tm = 0; tm < 2; tm++)
#pragma unroll
            for (int mt = 0; mt < 4; mt++) {
                int row = wm * 64 + mt * 16 + (lane & 15);
                int ch = kk * 2 + (lane >> 4);
                LDSM4(af[tm][mt], ab + tm * 16384 + row * 128 + ((ch ^ (row & 7)) << 4));
            }
        uint32_t bf[2][8];
#pragma unroll
        for (int j = 0; j < 2; j++)
#pragma unroll
            for (int q = 0; q < 2; q++) {
                int nrow = wn * 32 + q * 16 + (lane & 7) + ((lane & 16) ? 8 : 0);
                int ch = kk * 2 + ((lane >> 3) & 1);
                LDSM4(&bf[j][q * 4], pb + j * 8192 + nrow * 128 + ((ch ^ (nrow & 7)) << 4));
            }
#pragma unroll
        for (int j = 0; j < 2; j++) {
            const int ni = (j == 0) ? 2 : 1;           // a0b0, a1b0, a0b1
#pragma unroll
            for (int i = 0; i < 2; i++) {
                if (i >= ni) break;
#pragma unroll
                for (int mt = 0; mt < 4; mt++)
#pragma unroll
                    for (int nt = 0; nt < 4; nt++) {
                        int q = nt >> 1, o = (nt & 1) * 2;
                        MMA16816(acc[mt][nt], af[i][mt], bf[j][q * 4 + o], bf[j][q * 4 + o + 1]);
                    }
            }
        }
    }
}

__global__ void __launch_bounds__(NT, 2) rnn_mma_kernel(
    const int*   __restrict__ ids,   const float* __restrict__ emb,
    const float* __restrict__ w_xh0, const float* __restrict__ w_hh0,
    const float* __restrict__ b_h0,  const float* __restrict__ w_xh1,
    const float* __restrict__ w_hh1, const float* __restrict__ b_h1,
    const float* __restrict__ w_hy,  const float* __restrict__ b_y,
    float* __restrict__ out, long long out_size)
{
    extern __shared__ __align__(16) char dynsm[];
    const int bid = blockIdx.x;
    const int tid = threadIdx.x;
    const int lane = tid & 31;
    const int warp = tid >> 5;
    const int wm = warp >> 1, wn = warp & 1;           // 2M x 2N, warp tile 64x32
    const uint32_t dyn = (smem_u32(dynsm) + 1023u) & ~1023u;
    const long long full = (long long)BTV + 2LL * BH;

    unsigned long long ep = g_ep[bid];

    // ---- roles (uniform 6.3M-MAC jobs, tile 128x64, K=256) ----
    // role0: bid   0..63 : P0  = h0 @ w_hh0^T  (16n x 4kc)
    // role1: bid  64..127: P1a = h0 @ w_xh1^T
    // role2: bid 128..191: P1b = h1 @ w_hh1^T
    // role3: bid 192..223: Py  = h1 @ w_hy^T   (8n x 4kc)
    const int role = (bid < 64) ? 0 : (bid < 128) ? 1 : (bid < 192) ? 2 : 3;
    int n0, kbeg, pstride;
    const __nv_bfloat16 *Bs0, *Bs1;
    float* pdst;
    if (role == 0) {
        n0 = (bid >> 2) * 64; int kc = bid & 3;
        kbeg = kc * 256; Bs0 = g_w0sp[0]; Bs1 = g_w0sp[1];
        pdst = g_P0p[kc]; pstride = HH;
    } else if (role == 1) {
        int j = bid - 64; n0 = (j >> 2) * 64; int kc = j & 3;
        kbeg = kc * 256; Bs0 = g_w1sp[0]; Bs1 = g_w1sp[1];
        pdst = g_P1p[kc]; pstride = HH;
    } else if (role == 2) {
        int j = bid - 128; n0 = (j >> 2) * 64; int kc = j & 3;
        kbeg = kc * 256; Bs0 = g_w2sp[0]; Bs1 = g_w2sp[1];
        pdst = g_P1p[4 + kc]; pstride = HH;
    } else {
        int j = bid - 192; n0 = (j >> 2) * 64; int kc = j & 3;
        kbeg = kc * 256; Bs0 = g_wysp[0]; Bs1 = g_wysp[1];
        pdst = g_Py[kc]; pstride = VV;
    }

    // ============ prologue ============
    {
        const float* W[4] = {w_hh0, w_xh1, w_hh1, w_hy};
        __nv_bfloat16* S0[4] = {g_w0sp[0], g_w1sp[0], g_w2sp[0], g_wysp[0]};
        __nv_bfloat16* S1[4] = {g_w0sp[1], g_w1sp[1], g_w2sp[1], g_wysp[1]};
        const int SZ[4] = {HH * HH, HH * HH, HH * HH, VV * HH};
#pragma unroll
        for (int w = 0; w < 4; w++)
            for (int i = bid * NT + tid; i < SZ[w]; i += NB * NT)
                split2(W[w][i], S0[w][i], S1[w][i]);
        for (int i = bid * NT + tid; i < BH; i += NB * NT) {   // h1_{-1} = 0
            g_h1sp[0][i] = __float2bfloat16(0.f);
            g_h1sp[1][i] = __float2bfloat16(0.f);
        }
    }
    if (bid < 128) {   // tokproj: 128 tiles of 64x64
        float* sA = (float*)dynsm;
        float* sB = sA + 32 * 68;
        int m0 = (bid & 7) * 64, n0t = (bid >> 3) * 64;
        gemm64(sA, sB, EE,
            [&](int r, int k) { return emb[(m0 + r) * EE + k]; },
            [&](int r, int k) { return w_xh0[(n0t + r) * EE + k]; },
            [&](int m, int n, float4 v) {
                int col = n0t + n;
                float4 bb = *(const float4*)(b_h0 + col);
                v.x += bb.x; v.y += bb.y; v.z += bb.z; v.w += bb.w;
                *(float4*)(g_tokproj + (size_t)(m0 + m) * HH + col) = v;
            });
    }
    grid_bar(ep);

    // ---- persistent B slab: 4 chunks x (2 terms x 64 rows x 128B) ----
    for (int x = tid; x < 4096; x += NT) {
        int c = x >> 10, rem = x & 1023, j = rem >> 9, r = (rem >> 3) & 63, seg = x & 7;
        const __nv_bfloat16* s = (j ? Bs1 : Bs0)
            + (size_t)(n0 + r) * HH + kbeg + c * 64 + seg * 8;
        uint4 v = *(const uint4*)s;
        STS128(dyn + c * BCH + j * 8192 + r * 128 + ((seg ^ (r & 7)) << 4),
               v.x, v.y, v.z, v.w);
    }
    __syncthreads();

    // ============ main loop: t = 0 .. TT ============
    for (int t = 0; t <= TT; t++) {
        // ---- E phase (blocks 0..127, batch row = bid) ----
        if (bid < 128) {
            if (t >= 1) {                  // h1_{t-1}
#pragma unroll
                for (int it = 0; it < 2; it++) {
                    const int i = tid * 4 + it * 512;
                    const size_t idx = (size_t)bid * HH + i;
                    float4 s = *(const float4*)(b_h1 + i);
#pragma unroll
                    for (int k = 0; k < 8; k++) {
                        float4 p = __ldcg((const float4*)&g_P1p[k][idx]);
                        s.x += p.x; s.y += p.y; s.z += p.z; s.w += p.w;
                    }
                    float4 v;
                    v.x = tanhf(s.x); v.y = tanhf(s.y); v.z = tanhf(s.z); v.w = tanhf(s.w);
                    st_split4(g_h1sp[0], g_h1sp[1], idx, v);
                    if (t == TT && out_size >= full) *(float4*)&out[BTV + BH + idx] = v;
                }
            }
            if (t < TT) {                  // h0_t
                const int id_tok = ids[bid * TT + t];
#pragma unroll
                for (int it = 0; it < 2; it++) {
                    const int i = tid * 4 + it * 512;
                    const size_t idx = (size_t)bid * HH + i;
                    float4 s = *(const float4*)(g_tokproj + (size_t)id_tok * HH + i);
                    if (t > 0) {
#pragma unroll
                        for (int k = 0; k < 4; k++) {
                            float4 p = __ldcg((const float4*)&g_P0p[k][idx]);
                            s.x += p.x; s.y += p.y; s.z += p.z; s.w += p.w;
                        }
                    }
                    float4 v;
                    v.x = tanhf(s.x); v.y = tanhf(s.y); v.z = tanhf(s.z); v.w = tanhf(s.w);
                    st_split4(g_h0sp[0], g_h0sp[1], idx, v);
                    if (t == TT - 1 && out_size >= full) *(float4*)&out[BTV + idx] = v;
                }
            }
            if (t >= 2) {                  // logits row t-2
                const int v0 = tid * 4;
                const size_t pidx = (size_t)bid * VV + v0;
                float4 r = *(const float4*)(b_y + v0);
#pragma unroll
                for (int k = 0; k < 4; k++) {
                    float4 p = __ldcg((const float4*)&g_Py[k][pidx]);
                    r.x += p.x; r.y += p.y; r.z += p.z; r.w += p.w;
                }
                *(float4*)&out[((size_t)bid * TT + (t - 2)) * VV + v0] = r;
            }
        }
        grid_bar(ep);

        // ---- G phase ----
        bool doG;
        const __nv_bfloat16 *A0, *A1;
        if (role == 0)      { doG = (t < TT - 1); A0 = g_h0sp[0]; A1 = g_h0sp[1]; }
        else if (role == 1) { doG = (t < TT);     A0 = g_h0sp[0]; A1 = g_h0sp[1]; }
        else if (role == 2) { doG = (t < TT);     A0 = g_h1sp[0]; A1 = g_h1sp[1]; }
        else                { doG = (t >= 1);     A0 = g_h1sp[0]; A1 = g_h1sp[1]; }
        if (doG) {
            float acc[4][4][4];
#pragma unroll
            for (int a = 0; a < 4; a++)
#pragma unroll
                for (int b = 0; b < 4; b++)
#pragma unroll
                    for (int c = 0; c < 4; c++) acc[a][b][c] = 0.f;
            for (int c = 0; c < 4; c++) {
                stage_a(dyn + AB0, A0, A1, kbeg + c * 64);
                CP_WAIT0();
                __syncthreads();
                chunk_mma(acc, dyn + AB0, dyn + c * BCH, wm, wn, lane);
                __syncthreads();
            }
#pragma unroll
            for (int mt = 0; mt < 4; mt++)
#pragma unroll
                for (int nt = 0; nt < 4; nt++) {
                    int r = wm * 64 + mt * 16 + (lane >> 2);
                    int cc = wn * 32 + nt * 8 + (lane & 3) * 2;
                    *(float2*)(pdst + (size_t)r * pstride + n0 + cc) =
                        make_float2(acc[mt][nt][0], acc[mt][nt][1]);
                    *(float2*)(pdst + (size_t)(r + 8) * pstride + n0 + cc) =
                        make_float2(acc[mt][nt][2], acc[mt][nt][3]);
                }
        }
        grid_bar(ep);
    }

    // ---- post-loop: logits row TT-1 ----
    if (bid < 128) {
        const int v0 = tid * 4;
        const size_t pidx = (size_t)bid * VV + v0;
        float4 r = *(const float4*)(b_y + v0);
#pragma unroll
        for (int k = 0; k < 4; k++) {
            float4 p = __ldcg((const float4*)&g_Py[k][pidx]);
            r.x += p.x; r.y += p.y; r.z += p.z; r.w += p.w;
        }
        *(float4*)&out[((size_t)bid * TT + (TT - 1)) * VV + v0] = r;
    }
    if (tid == 0) g_ep[bid] = ep;
}

extern "C" void kernel_launch(void* const* d_in, const int* in_sizes, int n_in,
                              void* d_out, int out_size) {
    const int*   ids   = (const int*)d_in[0];
    const float* emb   = (const float*)d_in[1];
    const float* w_xh0 = (const float*)d_in[2];
    const float* w_hh0 = (const float*)d_in[3];
    const float* b_h0  = (const float*)d_in[4];
    const float* w_xh1 = (const float*)d_in[5];
    const float* w_hh1 = (const float*)d_in[6];
    const float* b_h1  = (const float*)d_in[7];
    const float* w_hy  = (const float*)d_in[8];
    const float* b_y   = (const float*)d_in[9];
    float* out = (float*)d_out;

    cudaFuncSetAttribute(rnn_mma_kernel, cudaFuncAttributeMaxDynamicSharedMemorySize,
                         DYNB_ALLOC);
    rnn_mma_kernel<<<NB, NT, DYNB_ALLOC>>>(ids, emb, w_xh0, w_hh0, b_h0,
                                           w_xh1, w_hh1, b_h1, w_hy, b_y,
                                           out, (long long)out_size);
}

// round 15
// speedup vs baseline: 1.4143x; 1.4143x over previous
#include <cuda_runtime.h>
#include <cuda_bf16.h>
#include <cstdint>

#define BB 128
#define TT 1024
#define EE 512
#define HH 1024
#define VV 512
#define NB 128
#define NT 256
#define BH (BB*HH)
#define BTV ((size_t)BB*TT*VV)

#define BCH    16384           // one persistent-B chunk: 2 terms x 64 rows x 128B
#define AB0    131072          // A staging after persistent B (8 chunks x 16KB)
#define ABSZ   32768
#define DYNB_ALLOC (AB0 + 2*ABSZ + 1024)

__device__ __align__(16) float g_tokproj[VV * HH];
__device__ __align__(16) float g_P0p[2][BH];
__device__ __align__(16) float g_P1p[4][BH];            // P1a 0-1, P1b 2-3
__device__ __align__(16) float g_Py[4][BB * VV];
__device__ __align__(16) __nv_bfloat16 g_h0sp[2][BH];
__device__ __align__(16) __nv_bfloat16 g_h1sp[2][BH];
__device__ __align__(16) __nv_bfloat16 g_w0sp[2][HH * HH];
__device__ __align__(16) __nv_bfloat16 g_w1sp[2][HH * HH];
__device__ __align__(16) __nv_bfloat16 g_w2sp[2][HH * HH];
__device__ __align__(16) __nv_bfloat16 g_wysp[2][VV * HH];
__device__ unsigned long long g_br[8];
__device__ unsigned long long g_ep[NB];

__device__ __forceinline__ uint32_t smem_u32(const void* p) {
    uint32_t a;
    asm("{ .reg .u64 t; cvta.to.shared.u64 t, %1; cvt.u32.u64 %0, t; }" : "=r"(a) : "l"(p));
    return a;
}
__device__ __forceinline__ void cp16(uint32_t dst, const void* src) {
    asm volatile("cp.async.cg.shared.global [%0], [%1], 16;" :: "r"(dst), "l"(src) : "memory");
}
#define CP_COMMIT() asm volatile("cp.async.commit_group;" ::: "memory")
#define CP_WAIT1()  asm volatile("cp.async.wait_group 1;" ::: "memory")
#define CP_WAIT0()  asm volatile("cp.async.wait_group 0;" ::: "memory")
#define STS128(a, x, y, z, w) \
    asm volatile("st.shared.v4.b32 [%0], {%1,%2,%3,%4};" \
                 :: "r"(a), "r"(x), "r"(y), "r"(z), "r"(w) : "memory")
#define LDSM4(r, a) \
    asm volatile("ldmatrix.sync.aligned.m8n8.x4.shared.b16 {%0,%1,%2,%3}, [%4];" \
        : "=r"((r)[0]), "=r"((r)[1]), "=r"((r)[2]), "=r"((r)[3]) : "r"(a))
#define MMA16816(c, a, b0r, b1r) \
    asm volatile("mma.sync.aligned.m16n8k16.row.col.f32.bf16.bf16.f32 " \
        "{%0,%1,%2,%3}, {%4,%5,%6,%7}, {%8,%9}, {%0,%1,%2,%3};" \
        : "+f"((c)[0]), "+f"((c)[1]), "+f"((c)[2]), "+f"((c)[3]) \
        : "r"((a)[0]), "r"((a)[1]), "r"((a)[2]), "r"((a)[3]), "r"(b0r), "r"(b1r))

__device__ __forceinline__ void grid_bar(unsigned long long& ep) {
    ep += (unsigned long long)NB;
    __syncthreads();
    if (threadIdx.x == 0) {
        __threadfence();
        atomicAdd(&g_br[blockIdx.x & 7], 1ULL);
        for (;;) {
            unsigned long long s = 0;
#pragma unroll
            for (int i = 0; i < 8; i++) s += *(volatile unsigned long long*)&g_br[i];
            if (s >= ep) break;
            __nanosleep(16);
        }
        __threadfence();
    }
    __syncthreads();
}

__device__ __forceinline__ void split2(float x, __nv_bfloat16& d0, __nv_bfloat16& d1) {
    __nv_bfloat16 b0 = __float2bfloat16(x);
    d0 = b0;
    d1 = __float2bfloat16(x - __bfloat162float(b0));
}
__device__ __forceinline__ void st_split4(__nv_bfloat16* d0, __nv_bfloat16* d1,
                                          size_t idx, float4 v) {
    __nv_bfloat16 a0, b0, a1, b1, a2, b2, a3, b3;
    split2(v.x, a0, b0); split2(v.y, a1, b1);
    split2(v.z, a2, b2); split2(v.w, a3, b3);
    __nv_bfloat162 lo0(a0, a1), hi0(a2, a3), lo1(b0, b1), hi1(b2, b3);
    *(uint2*)(d0 + idx) = make_uint2(*(uint32_t*)&lo0, *(uint32_t*)&hi0);
    *(uint2*)(d1 + idx) = make_uint2(*(uint32_t*)&lo1, *(uint32_t*)&hi1);
}

// SIMT fp32 64x64 GEMM (tokproj prologue only, NT=256)
template <typename LA, typename LB, typename ST>
__device__ __forceinline__ void gemm64(float* sA, float* sB, int kend, LA la, LB lb, ST st) {
    const int tid = threadIdx.x;
    const int tx = tid & 15, ty = tid >> 4;
    float acc[4][4];
#pragma unroll
    for (int i = 0; i < 4; i++)
#pragma unroll
        for (int j = 0; j < 4; j++) acc[i][j] = 0.f;
    for (int k0 = 0; k0 < kend; k0 += 32) {
#pragma unroll
        for (int i = 0; i < 8; i++) {
            int idx = tid + i * NT;
            int k = idx & 31, r = idx >> 5;
            sA[k * 68 + r] = la(r, k0 + k);
            sB[k * 68 + r] = lb(r, k0 + k);
        }
        __syncthreads();
#pragma unroll
        for (int kk = 0; kk < 32; kk++) {
            float4 a = *(const float4*)(sA + kk * 68 + 4 * ty);
            float4 b = *(const float4*)(sB + kk * 68 + 4 * tx);
            float av[4] = {a.x, a.y, a.z, a.w};
            float bv[4] = {b.x, b.y, b.z, b.w};
#pragma unroll
            for (int i = 0; i < 4; i++)
#pragma unroll
                for (int j = 0; j < 4; j++) acc[i][j] = fmaf(av[i], bv[j], acc[i][j]);
        }
        __syncthreads();
    }
#pragma unroll
    for (int i = 0; i < 4; i++)
        st(4 * ty + i, 4 * tx, make_float4(acc[i][0], acc[i][1], acc[i][2], acc[i][3]));
}

// stage one A chunk: 2 terms x 128 rows x 64 K-cols -> 32KB
__device__ __forceinline__ void stage_a(uint32_t ab, const __nv_bfloat16* A0,
                                        const __nv_bfloat16* A1, int kg) {
    const int tid = threadIdx.x;
#pragma unroll
    for (int it = 0; it < 8; it++) {
        int id = tid + it * NT;
        int i = id >> 10, rem = id & 1023, r = rem >> 3, seg = rem & 7;
        const __nv_bfloat16* s = (i ? A1 : A0) + (size_t)r * HH + kg + seg * 8;
        cp16(ab + i * 16384 + r * 128 + ((seg ^ (r & 7)) << 4), s);
    }
    CP_COMMIT();
}

// K=64 chunk, job 128x64: 8 warps = 4M(32) x 2N(32), warp tile 32x32, 3 products
__device__ __forceinline__ void chunk_mma(float acc[2][4][4], uint32_t ab, uint32_t pb,
                                          int wm, int wn, int lane) {
#pragma unroll
    for (int kk = 0; kk < 4; kk++) {
        uint32_t af[2][2][4];
#pragma unroll
        for (int tm = 0; tm < 2; tm++)
#pragma unroll
            for (int mt = 0; mt < 2; mt++) {
                int row = wm * 32 + mt * 16 + (lane & 15);
                int ch = kk * 2 + (lane >> 4);
                LDSM4(af[tm][mt], ab + tm * 16384 + row * 128 + ((ch ^ (row & 7)) << 4));
            }
        uint32_t bf[2][8];
#pragma unroll
        for (int j = 0; j < 2; j++)
#pragma unroll
            for (int q = 0; q < 2; q++) {
                int nrow = wn * 32 + q * 16 + (lane & 7) + ((lane & 16) ? 8 : 0);
                int ch = kk * 2 + ((lane >> 3) & 1);
                LDSM4(&bf[j][q * 4], pb + j * 8192 + nrow * 128 + ((ch ^ (nrow & 7)) << 4));
            }
#pragma unroll
        for (int j = 0; j < 2; j++) {
            const int ni = (j == 0) ? 2 : 1;          // terms: a0b0, a1b0, a0b1
#pragma unroll
            for (int i = 0; i < 2; i++) {
                if (i >= ni) break;
#pragma unroll
                for (int mt = 0; mt < 2; mt++)
#pragma unroll
                    for (int nt = 0; nt < 4; nt++) {
                        int q = nt >> 1, o = (nt & 1) * 2;
                        MMA16816(acc[mt][nt], af[i][mt], bf[j][q * 4 + o], bf[j][q * 4 + o + 1]);
                    }
            }
        }
    }
}

// tensor job: D[128,64] = 3-term A@B^T over nchunk K-chunks, B persistent in smem
template <typename EPI>
__device__ __forceinline__ void mma_job(
    const __nv_bfloat16* __restrict__ A0, const __nv_bfloat16* __restrict__ A1,
    int kglob0, int nchunk, uint32_t dyn, EPI epi)
{
    const int tid = threadIdx.x;
    const int lane = tid & 31;
    const int warp = tid >> 5;
    const int wm = warp >> 1, wn = warp & 1;

    float acc[2][4][4];
#pragma unroll
    for (int a = 0; a < 2; a++)
#pragma unroll
        for (int b = 0; b < 4; b++)
#pragma unroll
            for (int c = 0; c < 4; c++) acc[a][b][c] = 0.f;

    stage_a(dyn + AB0, A0, A1, kglob0);
    if (nchunk > 1) stage_a(dyn + AB0 + ABSZ, A0, A1, kglob0 + 64);
    for (int c = 0; c < nchunk; c++) {
        if (c + 1 < nchunk) { CP_WAIT1(); } else { CP_WAIT0(); }
        __syncthreads();
        chunk_mma(acc, dyn + AB0 + (c & 1) * ABSZ, dyn + c * BCH, wm, wn, lane);
        __syncthreads();
        if (c + 2 < nchunk) stage_a(dyn + AB0 + (c & 1) * ABSZ, A0, A1,
                                    kglob0 + (c + 2) * 64);
    }
#pragma unroll
    for (int mt = 0; mt < 2; mt++)
#pragma unroll
        for (int nt = 0; nt < 4; nt++) {
            int r = wm * 32 + mt * 16 + (lane >> 2);
            int cc = wn * 32 + nt * 8 + (lane & 3) * 2;
            epi(r, cc, acc[mt][nt][0], acc[mt][nt][1]);
            epi(r + 8, cc, acc[mt][nt][2], acc[mt][nt][3]);
        }
}

__global__ void __launch_bounds__(NT, 1) rnn_mma_kernel(
    const int*   __restrict__ ids,   const float* __restrict__ emb,
    const float* __restrict__ w_xh0, const float* __restrict__ w_hh0,
    const float* __restrict__ b_h0,  const float* __restrict__ w_xh1,
    const float* __restrict__ w_hh1, const float* __restrict__ b_h1,
    const float* __restrict__ w_hy,  const float* __restrict__ b_y,
    float* __restrict__ out, long long out_size)
{
    extern __shared__ __align__(16) char dynsm[];
    const int bid = blockIdx.x;
    const int tid = threadIdx.x;
    const uint32_t dyn = (smem_u32(dynsm) + 1023u) & ~1023u;
    const long long full = (long long)BTV + 2LL * BH;

    unsigned long long ep = g_ep[bid];

    // ---- fixed job assignment (R12 layout) ----
    // role 0: bid 0..31   P0  = h0 @ w_hh0^T   (16 n x 2 kc, K=512)
    // role 1: bid 32..63  P1a = h0 @ w_xh1^T
    // role 2: bid 64..95  P1b = h1 @ w_hh1^T
    // role 3: bid 96..127 LOG = h1 @ w_hy^T    (8 n x 4 kc, K=256)
    int role, n0, kbeg, nch, pstride;
    const __nv_bfloat16 *Bs0, *Bs1;
    float* pdst;
    if (bid < 32) {
        role = 0; n0 = (bid & 15) * 64; int kc = bid >> 4;
        kbeg = kc * 512; nch = 8; Bs0 = g_w0sp[0]; Bs1 = g_w0sp[1];
        pdst = g_P0p[kc]; pstride = HH;
    } else if (bid < 64) {
        role = 1; int j = bid - 32; n0 = (j & 15) * 64; int kc = j >> 4;
        kbeg = kc * 512; nch = 8; Bs0 = g_w1sp[0]; Bs1 = g_w1sp[1];
        pdst = g_P1p[kc]; pstride = HH;
    } else if (bid < 96) {
        role = 2; int j = bid - 64; n0 = (j & 15) * 64; int kc = j >> 4;
        kbeg = kc * 512; nch = 8; Bs0 = g_w2sp[0]; Bs1 = g_w2sp[1];
        pdst = g_P1p[2 + kc]; pstride = HH;
    } else {
        role = 3; int j = bid - 96; n0 = (j >> 2) * 64; int kc = j & 3;
        kbeg = kc * 256; nch = 4; Bs0 = g_wysp[0]; Bs1 = g_wysp[1];
        pdst = g_Py[kc]; pstride = VV;
    }

    // ============ prologue ============
    {
        const float* W[4] = {w_hh0, w_xh1, w_hh1, w_hy};
        __nv_bfloat16* S0[4] = {g_w0sp[0], g_w1sp[0], g_w2sp[0], g_wysp[0]};
        __nv_bfloat16* S1[4] = {g_w0sp[1], g_w1sp[1], g_w2sp[1], g_wysp[1]};
        const int SZ[4] = {HH * HH, HH * HH, HH * HH, VV * HH};
#pragma unroll
        for (int w = 0; w < 4; w++)
            for (int i = bid * NT + tid; i < SZ[w]; i += NB * NT)
                split2(W[w][i], S0[w][i], S1[w][i]);
        for (int i = bid * NT + tid; i < BH; i += NB * NT) {   // h1_{-1} = 0
            g_h1sp[0][i] = __float2bfloat16(0.f);
            g_h1sp[1][i] = __float2bfloat16(0.f);
        }
    }
    {   // tokproj[v][h] = b_h0[h] + emb[v] . w_xh0[h]
        float* sA = (float*)dynsm;
        float* sB = sA + 32 * 68;
        int m0 = (bid & 7) * 64, n0t = (bid >> 3) * 64;
        gemm64(sA, sB, EE,
            [&](int r, int k) { return emb[(m0 + r) * EE + k]; },
            [&](int r, int k) { return w_xh0[(n0t + r) * EE + k]; },
            [&](int m, int n, float4 v) {
                int col = n0t + n;
                float4 bb = *(const float4*)(b_h0 + col);
                v.x += bb.x; v.y += bb.y; v.z += bb.z; v.w += bb.w;
                *(float4*)(g_tokproj + (size_t)(m0 + m) * HH + col) = v;
            });
    }
    grid_bar(ep);

    // ---- persistent B slabs: nch chunks x (2 terms x 64 rows x 128B) ----
    {
        const int total = nch * 1024;
        for (int x = tid; x < total; x += NT) {
            int c = x >> 10, rem = x & 1023;
            int jt = rem >> 9, r = (rem >> 3) & 63, seg = rem & 7;
            const __nv_bfloat16* s = (jt ? Bs1 : Bs0)
                + (size_t)(n0 + r) * HH + kbeg + c * 64 + seg * 8;
            uint4 v = *(const uint4*)s;
            STS128(dyn + c * BCH + jt * 8192 + r * 128 + ((seg ^ (r & 7)) << 4),
                   v.x, v.y, v.z, v.w);
        }
        __syncthreads();
    }

    auto epi_part = [&](int r, int c, float v0, float v1) {
        *(float2*)(pdst + (size_t)r * pstride + n0 + c) = make_float2(v0, v1);
    };

    // ============ pipelined loop: t = 0 .. TT ============
    for (int t = 0; t <= TT; t++) {
        // ---- E phase (block = batch row bid) ----
        {
            if (tid < 256) {
                if (t > 0) {               // finalize h1_{t-1}
                    const int i = tid * 4;
                    const size_t idx = (size_t)bid * HH + i;
                    float4 a = __ldcg((const float4*)&g_P1p[0][idx]);
                    float4 b = __ldcg((const float4*)&g_P1p[1][idx]);
                    float4 c = __ldcg((const float4*)&g_P1p[2][idx]);
                    float4 d = __ldcg((const float4*)&g_P1p[3][idx]);
                    float4 bb = *(const float4*)(b_h1 + i);
                    float4 v;
                    v.x = tanhf(bb.x + a.x + b.x + c.x + d.x);
                    v.y = tanhf(bb.y + a.y + b.y + c.y + d.y);
                    v.z = tanhf(bb.z + a.z + b.z + c.z + d.z);
                    v.w = tanhf(bb.w + a.w + b.w + c.w + d.w);
                    st_split4(g_h1sp[0], g_h1sp[1], idx, v);
                    if (t == TT && out_size >= full)
                        *(float4*)&out[BTV + BH + idx] = v;          // final h1
                }
                if (t < TT) {              // compute h0_t (second 512 cols)
                    const int i = tid * 4 + 0;
                    // handled below by all threads: see unified loop
                }
            }
            // h0_t: one float4 per thread over 1024 cols (256 threads x 4)
            if (t < TT) {
                const int i = tid * 4;
                const size_t idx = (size_t)bid * HH + i;
                const int id_tok = ids[bid * TT + t];
                float4 s = *(const float4*)(g_tokproj + (size_t)id_tok * HH + i);
                if (t > 0) {
                    float4 a = __ldcg((const float4*)&g_P0p[0][idx]);
                    float4 b = __ldcg((const float4*)&g_P0p[1][idx]);
                    s.x += a.x + b.x; s.y += a.y + b.y;
                    s.z += a.z + b.z; s.w += a.w + b.w;
                }
                float4 v;
                v.x = tanhf(s.x); v.y = tanhf(s.y);
                v.z = tanhf(s.z); v.w = tanhf(s.w);
                st_split4(g_h0sp[0], g_h0sp[1], idx, v);
                if (t == TT - 1 && out_size >= full)
                    *(float4*)&out[BTV + idx] = v;                   // final h0
            }
            if (t >= 2) {                  // reduce logits for step t-2
                const int v0 = tid * 2;
                const size_t pidx = (size_t)bid * VV + v0;
                float2 r = *(const float2*)(b_y + v0);
#pragma unroll
                for (int k = 0; k < 4; k++) {
                    float2 p = __ldcg((const float2*)&g_Py[k][pidx]);
                    r.x += p.x; r.y += p.y;
                }
                *(float2*)&out[((size_t)bid * TT + (t - 2)) * VV + v0] = r;
            }
        }
        grid_bar(ep);

        // ---- G phase ----
        if (role == 0) {
            if (t < TT - 1) mma_job(g_h0sp[0], g_h0sp[1], kbeg, nch, dyn, epi_part);
        } else if (role == 1) {
            if (t < TT)     mma_job(g_h0sp[0], g_h0sp[1], kbeg, nch, dyn, epi_part);
        } else if (role == 2) {
            if (t < TT)     mma_job(g_h1sp[0], g_h1sp[1], kbeg, nch, dyn, epi_part);
        } else {
            if (t >= 1)     mma_job(g_h1sp[0], g_h1sp[1], kbeg, nch, dyn, epi_part);
        }
        grid_bar(ep);
    }

    // ============ post-loop: logits row TT-1 ============
    {
        const int v0 = tid * 2;
        const size_t pidx = (size_t)bid * VV + v0;
        float2 r = *(const float2*)(b_y + v0);
#pragma unroll
        for (int k = 0; k < 4; k++) {
            float2 p = __ldcg((const float2*)&g_Py[k][pidx]);
            r.x += p.x; r.y += p.y;
        }
        *(float2*)&out[((size_t)bid * TT + (TT - 1)) * VV + v0] = r;
    }
    if (tid == 0) g_ep[bid] = ep;
}

extern "C" void kernel_launch(void* const* d_in, const int* in_sizes, int n_in,
                              void* d_out, int out_size) {
    const int*   ids   = (const int*)d_in[0];
    const float* emb   = (const float*)d_in[1];
    const float* w_xh0 = (const float*)d_in[2];
    const float* w_hh0 = (const float*)d_in[3];
    const float* b_h0  = (const float*)d_in[4];
    const float* w_xh1 = (const float*)d_in[5];
    const float* w_hh1 = (const float*)d_in[6];
    const float* b_h1  = (const float*)d_in[7];
    const float* w_hy  = (const float*)d_in[8];
    const float* b_y   = (const float*)d_in[9];
    float* out = (float*)d_out;

    cudaFuncSetAttribute(rnn_mma_kernel, cudaFuncAttributeMaxDynamicSharedMemorySize,
                         DYNB_ALLOC);
    rnn_mma_kernel<<<NB, NT, DYNB_ALLOC>>>(ids, emb, w_xh0, w_hh0, b_h0,
                                           w_xh1, w_hh1, b_h1, w_hy, b_y,
                                           out, (long long)out_size);
}

// round 16
// speedup vs baseline: 1.6215x; 1.1465x over previous
#include <cuda_runtime.h>
#include <cuda_fp16.h>
#include <cstdint>

#define BB 128
#define TT 1024
#define EE 512
#define HH 1024
#define VV 512
#define NB 128
#define NT 256
#define BH (BB*HH)
#define BTV ((size_t)BB*TT*VV)

#define BCH    16384           // one persistent-B chunk: 2 terms x 64 rows x 128B
#define AB0    131072          // A staging after persistent B (max 8 chunks x 16KB)
#define ABSZ   16384           // A chunk: 1 term x 128 rows x 128B
#define DYNB_ALLOC (AB0 + 2*ABSZ + 1024)

__device__ __align__(16) float g_tokproj[VV * HH];
__device__ __align__(16) float g_P0p[2][BH];
__device__ __align__(16) float g_P1p[4][BH];            // P1a 0-1, P1b 2-3
__device__ __align__(16) float g_Py[4][BB * VV];
__device__ __align__(16) __half g_h0h[BH];              // single fp16 h0
__device__ __align__(16) __half g_h1h[BH];              // single fp16 h1
__device__ __align__(16) __half g_w0sp[2][HH * HH];     // w_hh0 fp16 split
__device__ __align__(16) __half g_w1sp[2][HH * HH];     // w_xh1
__device__ __align__(16) __half g_w2sp[2][HH * HH];     // w_hh1
__device__ __align__(16) __half g_wysp[2][VV * HH];     // w_hy
__device__ unsigned long long g_br[8];
__device__ unsigned long long g_ep[NB];

__device__ __forceinline__ uint32_t smem_u32(const void* p) {
    uint32_t a;
    asm("{ .reg .u64 t; cvta.to.shared.u64 t, %1; cvt.u32.u64 %0, t; }" : "=r"(a) : "l"(p));
    return a;
}
__device__ __forceinline__ void cp16(uint32_t dst, const void* src) {
    asm volatile("cp.async.cg.shared.global [%0], [%1], 16;" :: "r"(dst), "l"(src) : "memory");
}
#define CP_COMMIT() asm volatile("cp.async.commit_group;" ::: "memory")
#define CP_WAIT1()  asm volatile("cp.async.wait_group 1;" ::: "memory")
#define CP_WAIT0()  asm volatile("cp.async.wait_group 0;" ::: "memory")
#define STS128(a, x, y, z, w) \
    asm volatile("st.shared.v4.b32 [%0], {%1,%2,%3,%4};" \
                 :: "r"(a), "r"(x), "r"(y), "r"(z), "r"(w) : "memory")
#define LDSM4(r, a) \
    asm volatile("ldmatrix.sync.aligned.m8n8.x4.shared.b16 {%0,%1,%2,%3}, [%4];" \
        : "=r"((r)[0]), "=r"((r)[1]), "=r"((r)[2]), "=r"((r)[3]) : "r"(a))
#define MMA16816(c, a, b0r, b1r) \
    asm volatile("mma.sync.aligned.m16n8k16.row.col.f32.f16.f16.f32 " \
        "{%0,%1,%2,%3}, {%4,%5,%6,%7}, {%8,%9}, {%0,%1,%2,%3};" \
        : "+f"((c)[0]), "+f"((c)[1]), "+f"((c)[2]), "+f"((c)[3]) \
        : "r"((a)[0]), "r"((a)[1]), "r"((a)[2]), "r"((a)[3]), "r"(b0r), "r"(b1r))

__device__ __forceinline__ void grid_bar(unsigned long long& ep) {
    ep += (unsigned long long)NB;
    __syncthreads();
    if (threadIdx.x == 0) {
        __threadfence();
        atomicAdd(&g_br[blockIdx.x & 7], 1ULL);
        for (;;) {
            unsigned long long s = 0;
#pragma unroll
            for (int i = 0; i < 8; i++) s += *(volatile unsigned long long*)&g_br[i];
            if (s >= ep) break;
            __nanosleep(16);
        }
        __threadfence();
    }
    __syncthreads();
}

// fp16 weight split: w = w0 + w1 (w1 captures residual; subnormals fine)
__device__ __forceinline__ void wsplit(float x, __half& d0, __half& d1) {
    __half h0 = __float2half(x);
    d0 = h0;
    d1 = __float2half(x - __half2float(h0));
}
// store 4 fp16 h values (from float4)
__device__ __forceinline__ void st_h4(__half* d, size_t idx, float4 v) {
    __half2 lo(__float2half(v.x), __float2half(v.y));
    __half2 hi(__float2half(v.z), __float2half(v.w));
    *(uint2*)(d + idx) = make_uint2(*(uint32_t*)&lo, *(uint32_t*)&hi);
}

// SIMT fp32 64x64 GEMM (tokproj prologue only, NT=256)
template <typename LA, typename LB, typename ST>
__device__ __forceinline__ void gemm64(float* sA, float* sB, int kend, LA la, LB lb, ST st) {
    const int tid = threadIdx.x;
    const int tx = tid & 15, ty = tid >> 4;
    float acc[4][4];
#pragma unroll
    for (int i = 0; i < 4; i++)
#pragma unroll
        for (int j = 0; j < 4; j++) acc[i][j] = 0.f;
    for (int k0 = 0; k0 < kend; k0 += 32) {
#pragma unroll
        for (int i = 0; i < 8; i++) {
            int idx = tid + i * NT;
            int k = idx & 31, r = idx >> 5;
            sA[k * 68 + r] = la(r, k0 + k);
            sB[k * 68 + r] = lb(r, k0 + k);
        }
        __syncthreads();
#pragma unroll
        for (int kk = 0; kk < 32; kk++) {
            float4 a = *(const float4*)(sA + kk * 68 + 4 * ty);
            float4 b = *(const float4*)(sB + kk * 68 + 4 * tx);
            float av[4] = {a.x, a.y, a.z, a.w};
            float bv[4] = {b.x, b.y, b.z, b.w};
#pragma unroll
            for (int i = 0; i < 4; i++)
#pragma unroll
                for (int j = 0; j < 4; j++) acc[i][j] = fmaf(av[i], bv[j], acc[i][j]);
        }
        __syncthreads();
    }
#pragma unroll
    for (int i = 0; i < 4; i++)
        st(4 * ty + i, 4 * tx, make_float4(acc[i][0], acc[i][1], acc[i][2], acc[i][3]));
}

// stage one A chunk: 1 term x 128 rows x 64 K-cols -> 16KB
__device__ __forceinline__ void stage_a(uint32_t ab, const __half* A, int kg) {
    const int tid = threadIdx.x;
#pragma unroll
    for (int it = 0; it < 4; it++) {
        int id = tid + it * NT;                      // 0..1023
        int r = id >> 3, seg = id & 7;
        const __half* s = A + (size_t)r * HH + kg + seg * 8;
        cp16(ab + r * 128 + ((seg ^ (r & 7)) << 4), s);
    }
    CP_COMMIT();
}

// K=64 chunk, job 128x64: 8 warps = 4M(32) x 2N(32), 2 products (a0b0, a0b1)
__device__ __forceinline__ void chunk_mma(float acc[2][4][4], uint32_t ab, uint32_t pb,
                                          int wm, int wn, int lane) {
#pragma unroll
    for (int kk = 0; kk < 4; kk++) {
        uint32_t af[2][4];
#pragma unroll
        for (int mt = 0; mt < 2; mt++) {
            int row = wm * 32 + mt * 16 + (lane & 15);
            int ch = kk * 2 + (lane >> 4);
            LDSM4(af[mt], ab + row * 128 + ((ch ^ (row & 7)) << 4));
        }
        uint32_t bf[2][8];
#pragma unroll
        for (int j = 0; j < 2; j++)
#pragma unroll
            for (int q = 0; q < 2; q++) {
                int nrow = wn * 32 + q * 16 + (lane & 7) + ((lane & 16) ? 8 : 0);
                int ch = kk * 2 + ((lane >> 3) & 1);
                LDSM4(&bf[j][q * 4], pb + j * 8192 + nrow * 128 + ((ch ^ (nrow & 7)) << 4));
            }
#pragma unroll
        for (int j = 0; j < 2; j++)
#pragma unroll
            for (int mt = 0; mt < 2; mt++)
#pragma unroll
                for (int nt = 0; nt < 4; nt++) {
                    int q = nt >> 1, o = (nt & 1) * 2;
                    MMA16816(acc[mt][nt], af[mt], bf[j][q * 4 + o], bf[j][q * 4 + o + 1]);
                }
    }
}

// tensor job: D[128,64] = h_q @ (W0+W1)^T over nchunk K-chunks, B persistent in smem
template <typename EPI>
__device__ __forceinline__ void mma_job(const __half* __restrict__ A,
                                        int kglob0, int nchunk, uint32_t dyn, EPI epi) {
    const int tid = threadIdx.x;
    const int lane = tid & 31;
    const int warp = tid >> 5;
    const int wm = warp >> 1, wn = warp & 1;

    float acc[2][4][4];
#pragma unroll
    for (int a = 0; a < 2; a++)
#pragma unroll
        for (int b = 0; b < 4; b++)
#pragma unroll
            for (int c = 0; c < 4; c++) acc[a][b][c] = 0.f;

    stage_a(dyn + AB0, A, kglob0);
    if (nchunk > 1) stage_a(dyn + AB0 + ABSZ, A, kglob0 + 64);
    for (int c = 0; c < nchunk; c++) {
        if (c + 1 < nchunk) { CP_WAIT1(); } else { CP_WAIT0(); }
        __syncthreads();
        chunk_mma(acc, dyn + AB0 + (c & 1) * ABSZ, dyn + c * BCH, wm, wn, lane);
        __syncthreads();
        if (c + 2 < nchunk) stage_a(dyn + AB0 + (c & 1) * ABSZ, A, kglob0 + (c + 2) * 64);
    }
#pragma unroll
    for (int mt = 0; mt < 2; mt++)
#pragma unroll
        for (int nt = 0; nt < 4; nt++) {
            int r = wm * 32 + mt * 16 + (lane >> 2);
            int cc = wn * 32 + nt * 8 + (lane & 3) * 2;
            epi(r, cc, acc[mt][nt][0], acc[mt][nt][1]);
            epi(r + 8, cc, acc[mt][nt][2], acc[mt][nt][3]);
        }
}

__global__ void __launch_bounds__(NT, 1) rnn_mma_kernel(
    const int*   __restrict__ ids,   const float* __restrict__ emb,
    const float* __restrict__ w_xh0, const float* __restrict__ w_hh0,
    const float* __restrict__ b_h0,  const float* __restrict__ w_xh1,
    const float* __restrict__ w_hh1, const float* __restrict__ b_h1,
    const float* __restrict__ w_hy,  const float* __restrict__ b_y,
    float* __restrict__ out, long long out_size)
{
    extern __shared__ __align__(16) char dynsm[];
    const int bid = blockIdx.x;
    const int tid = threadIdx.x;
    const uint32_t dyn = (smem_u32(dynsm) + 1023u) & ~1023u;
    const long long full = (long long)BTV + 2LL * BH;

    unsigned long long ep = g_ep[bid];

    // ---- fixed job assignment (R12 layout) ----
    // role 0: bid 0..31   P0  = h0 @ w_hh0^T   (16 n x 2 kc, K=512, nch=8)
    // role 1: bid 32..63  P1a = h0 @ w_xh1^T
    // role 2: bid 64..95  P1b = h1 @ w_hh1^T
    // role 3: bid 96..127 LOG = h1 @ w_hy^T    (8 n x 4 kc, K=256, nch=4)
    int role, n0, kbeg, nch, pstride;
    const __half *Bs0, *Bs1;
    float* pdst;
    if (bid < 32) {
        role = 0; n0 = (bid & 15) * 64; int kc = bid >> 4;
        kbeg = kc * 512; nch = 8; Bs0 = g_w0sp[0]; Bs1 = g_w0sp[1];
        pdst = g_P0p[kc]; pstride = HH;
    } else if (bid < 64) {
        role = 1; int j = bid - 32; n0 = (j & 15) * 64; int kc = j >> 4;
        kbeg = kc * 512; nch = 8; Bs0 = g_w1sp[0]; Bs1 = g_w1sp[1];
        pdst = g_P1p[kc]; pstride = HH;
    } else if (bid < 96) {
        role = 2; int j = bid - 64; n0 = (j & 15) * 64; int kc = j >> 4;
        kbeg = kc * 512; nch = 8; Bs0 = g_w2sp[0]; Bs1 = g_w2sp[1];
        pdst = g_P1p[2 + kc]; pstride = HH;
    } else {
        role = 3; int j = bid - 96; n0 = (j >> 2) * 64; int kc = j & 3;
        kbeg = kc * 256; nch = 4; Bs0 = g_wysp[0]; Bs1 = g_wysp[1];
        pdst = g_Py[kc]; pstride = VV;
    }

    // ============ prologue ============
    {
        const float* W[4] = {w_hh0, w_xh1, w_hh1, w_hy};
        __half* S0[4] = {g_w0sp[0], g_w1sp[0], g_w2sp[0], g_wysp[0]};
        __half* S1[4] = {g_w0sp[1], g_w1sp[1], g_w2sp[1], g_wysp[1]};
        const int SZ[4] = {HH * HH, HH * HH, HH * HH, VV * HH};
#pragma unroll
        for (int w = 0; w < 4; w++)
            for (int i = bid * NT + tid; i < SZ[w]; i += NB * NT)
                wsplit(W[w][i], S0[w][i], S1[w][i]);
        for (int i = bid * NT + tid; i < BH; i += NB * NT)     // h1_{-1} = 0
            g_h1h[i] = __float2half(0.f);
    }
    {   // tokproj[v][h] = b_h0[h] + emb[v] . w_xh0[h]
        float* sA = (float*)dynsm;
        float* sB = sA + 32 * 68;
        int m0 = (bid & 7) * 64, n0t = (bid >> 3) * 64;
        gemm64(sA, sB, EE,
            [&](int r, int k) { return emb[(m0 + r) * EE + k]; },
            [&](int r, int k) { return w_xh0[(n0t + r) * EE + k]; },
            [&](int m, int n, float4 v) {
                int col = n0t + n;
                float4 bb = *(const float4*)(b_h0 + col);
                v.x += bb.x; v.y += bb.y; v.z += bb.z; v.w += bb.w;
                *(float4*)(g_tokproj + (size_t)(m0 + m) * HH + col) = v;
            });
    }
    grid_bar(ep);

    // ---- persistent B slabs: nch chunks x (2 terms x 64 rows x 128B) ----
    {
        const int total = nch * 1024;
        for (int x = tid; x < total; x += NT) {
            int c = x >> 10, rem = x & 1023;
            int jt = rem >> 9, r = (rem >> 3) & 63, seg = rem & 7;
            const __half* s = (jt ? Bs1 : Bs0)
                + (size_t)(n0 + r) * HH + kbeg + c * 64 + seg * 8;
            uint4 v = *(const uint4*)s;
            STS128(dyn + c * BCH + jt * 8192 + r * 128 + ((seg ^ (r & 7)) << 4),
                   v.x, v.y, v.z, v.w);
        }
        __syncthreads();
    }

    auto epi_part = [&](int r, int c, float v0, float v1) {
        *(float2*)(pdst + (size_t)r * pstride + n0 + c) = make_float2(v0, v1);
    };

    // ============ pipelined loop: t = 0 .. TT ============
    for (int t = 0; t <= TT; t++) {
        // ---- E phase (block = batch row bid) ----
        {
            if (t > 0) {                   // finalize h1_{t-1}
                const int i = tid * 4;
                const size_t idx = (size_t)bid * HH + i;
                float4 a = __ldcg((const float4*)&g_P1p[0][idx]);
                float4 b = __ldcg((const float4*)&g_P1p[1][idx]);
                float4 c = __ldcg((const float4*)&g_P1p[2][idx]);
                float4 d = __ldcg((const float4*)&g_P1p[3][idx]);
                float4 bb = *(const float4*)(b_h1 + i);
                float4 v;
                v.x = tanhf(bb.x + a.x + b.x + c.x + d.x);
                v.y = tanhf(bb.y + a.y + b.y + c.y + d.y);
                v.z = tanhf(bb.z + a.z + b.z + c.z + d.z);
                v.w = tanhf(bb.w + a.w + b.w + c.w + d.w);
                st_h4(g_h1h, idx, v);
                if (t == TT && out_size >= full)
                    *(float4*)&out[BTV + BH + idx] = v;              // final h1
            }
            if (t < TT) {                  // compute h0_t
                const int i = tid * 4;
                const size_t idx = (size_t)bid * HH + i;
                const int id_tok = ids[bid * TT + t];
                float4 s = *(const float4*)(g_tokproj + (size_t)id_tok * HH + i);
                if (t > 0) {
                    float4 a = __ldcg((const float4*)&g_P0p[0][idx]);
                    float4 b = __ldcg((const float4*)&g_P0p[1][idx]);
                    s.x += a.x + b.x; s.y += a.y + b.y;
                    s.z += a.z + b.z; s.w += a.w + b.w;
                }
                float4 v;
                v.x = tanhf(s.x); v.y = tanhf(s.y);
                v.z = tanhf(s.z); v.w = tanhf(s.w);
                st_h4(g_h0h, idx, v);
                if (t == TT - 1 && out_size >= full)
                    *(float4*)&out[BTV + idx] = v;                   // final h0
            }
            if (t >= 2) {                  // reduce logits for step t-2
                const int v0 = tid * 2;
                const size_t pidx = (size_t)bid * VV + v0;
                float2 r = *(const float2*)(b_y + v0);
#pragma unroll
                for (int k = 0; k < 4; k++) {
                    float2 p = __ldcg((const float2*)&g_Py[k][pidx]);
                    r.x += p.x; r.y += p.y;
                }
                *(float2*)&out[((size_t)bid * TT + (t - 2)) * VV + v0] = r;
            }
        }
        grid_bar(ep);

        // ---- G phase ----
        if (role == 0) {
            if (t < TT - 1) mma_job(g_h0h, kbeg, nch, dyn, epi_part);
        } else if (role == 1) {
            if (t < TT)     mma_job(g_h0h, kbeg, nch, dyn, epi_part);
        } else if (role == 2) {
            if (t < TT)     mma_job(g_h1h, kbeg, nch, dyn, epi_part);
        } else {
            if (t >= 1)     mma_job(g_h1h, kbeg, nch, dyn, epi_part);
        }
        grid_bar(ep);
    }

    // ============ post-loop: logits row TT-1 ============
    {
        const int v0 = tid * 2;
        const size_t pidx = (size_t)bid * VV + v0;
        float2 r = *(const float2*)(b_y + v0);
#pragma unroll
        for (int k = 0; k < 4; k++) {
            float2 p = __ldcg((const float2*)&g_Py[k][pidx]);
            r.x += p.x; r.y += p.y;
        }
        *(float2*)&out[((size_t)bid * TT + (TT - 1)) * VV + v0] = r;
    }
    if (tid == 0) g_ep[bid] = ep;
}

extern "C" void kernel_launch(void* const* d_in, const int* in_sizes, int n_in,
                              void* d_out, int out_size) {
    const int*   ids   = (const int*)d_in[0];
    const float* emb   = (const float*)d_in[1];
    const float* w_xh0 = (const float*)d_in[2];
    const float* w_hh0 = (const float*)d_in[3];
    const float* b_h0  = (const float*)d_in[4];
    const float* w_xh1 = (const float*)d_in[5];
    const float* w_hh1 = (const float*)d_in[6];
    const float* b_h1  = (const float*)d_in[7];
    const float* w_hy  = (const float*)d_in[8];
    const float* b_y   = (const float*)d_in[9];
    float* out = (float*)d_out;

    cudaFuncSetAttribute(rnn_mma_kernel, cudaFuncAttributeMaxDynamicSharedMemorySize,
                         DYNB_ALLOC);
    rnn_mma_kernel<<<NB, NT, DYNB_ALLOC>>>(ids, emb, w_xh0, w_hh0, b_h0,
                                           w_xh1, w_hh1, b_h1, w_hy, b_y,
                                           out, (long long)out_size);
}

// round 17
// speedup vs baseline: 1.6962x; 1.0461x over previous
#include <cuda_runtime.h>
#include <cuda_fp16.h>
#include <cstdint>

#define BB 128
#define TT 1024
#define EE 512
#define HH 1024
#define VV 512
#define NB 128
#define NT 256
#define BH (BB*HH)
#define BTV ((size_t)BB*TT*VV)

#define BCH    16384           // persistent-B sub-slab: 2 terms x 64 rows x 128B (K=64)
#define AB0    131072          // A staging after persistent B (max 8 sub-slabs x 16KB)
#define ABSZ   32768           // A big-chunk: 2 sub-slabs (K=128)
#define DYNB_ALLOC (AB0 + 2*ABSZ + 1024)

__device__ __align__(16) float g_tokproj[VV * HH];
__device__ __align__(16) float g_P0p[2][BH];
__device__ __align__(16) float g_P1p[4][BH];            // P1a 0-1, P1b 2-3
__device__ __align__(16) float g_Py[4][BB * VV];
__device__ __align__(16) __half g_h0h[BH];              // single fp16 h0
__device__ __align__(16) __half g_h1h[BH];              // single fp16 h1
__device__ __align__(16) __half g_w0sp[2][HH * HH];     // w_hh0 fp16 split
__device__ __align__(16) __half g_w1sp[2][HH * HH];     // w_xh1
__device__ __align__(16) __half g_w2sp[2][HH * HH];     // w_hh1
__device__ __align__(16) __half g_wysp[2][VV * HH];     // w_hy
__device__ unsigned long long g_br[8];
__device__ unsigned long long g_ep[NB];

__device__ __forceinline__ uint32_t smem_u32(const void* p) {
    uint32_t a;
    asm("{ .reg .u64 t; cvta.to.shared.u64 t, %1; cvt.u32.u64 %0, t; }" : "=r"(a) : "l"(p));
    return a;
}
__device__ __forceinline__ void cp16(uint32_t dst, const void* src) {
    asm volatile("cp.async.cg.shared.global [%0], [%1], 16;" :: "r"(dst), "l"(src) : "memory");
}
#define CP_COMMIT() asm volatile("cp.async.commit_group;" ::: "memory")
#define CP_WAIT1()  asm volatile("cp.async.wait_group 1;" ::: "memory")
#define CP_WAIT0()  asm volatile("cp.async.wait_group 0;" ::: "memory")
#define STS128(a, x, y, z, w) \
    asm volatile("st.shared.v4.b32 [%0], {%1,%2,%3,%4};" \
                 :: "r"(a), "r"(x), "r"(y), "r"(z), "r"(w) : "memory")
#define LDSM4(r, a) \
    asm volatile("ldmatrix.sync.aligned.m8n8.x4.shared.b16 {%0,%1,%2,%3}, [%4];" \
        : "=r"((r)[0]), "=r"((r)[1]), "=r"((r)[2]), "=r"((r)[3]) : "r"(a))
#define MMA16816(c, a, b0r, b1r) \
    asm volatile("mma.sync.aligned.m16n8k16.row.col.f32.f16.f16.f32 " \
        "{%0,%1,%2,%3}, {%4,%5,%6,%7}, {%8,%9}, {%0,%1,%2,%3};" \
        : "+f"((c)[0]), "+f"((c)[1]), "+f"((c)[2]), "+f"((c)[3]) \
        : "r"((a)[0]), "r"((a)[1]), "r"((a)[2]), "r"((a)[3]), "r"(b0r), "r"(b1r))

__device__ __forceinline__ void grid_bar(unsigned long long& ep) {
    ep += (unsigned long long)NB;
    __syncthreads();
    if (threadIdx.x == 0) {
        __threadfence();
        atomicAdd(&g_br[blockIdx.x & 7], 1ULL);
        for (;;) {
            unsigned long long s = 0;
#pragma unroll
            for (int i = 0; i < 8; i++) s += *(volatile unsigned long long*)&g_br[i];
            if (s >= ep) break;
            __nanosleep(16);
        }
        __threadfence();
    }
    __syncthreads();
}

// fp16 weight split: w = w0 + w1
__device__ __forceinline__ void wsplit(float x, __half& d0, __half& d1) {
    __half h0 = __float2half(x);
    d0 = h0;
    d1 = __float2half(x - __half2float(h0));
}
__device__ __forceinline__ void st_h4(__half* d, size_t idx, float4 v) {
    __half2 lo(__float2half(v.x), __float2half(v.y));
    __half2 hi(__float2half(v.z), __float2half(v.w));
    *(uint2*)(d + idx) = make_uint2(*(uint32_t*)&lo, *(uint32_t*)&hi);
}

// SIMT fp32 64x64 GEMM (tokproj prologue only, NT=256)
template <typename LA, typename LB, typename ST>
__device__ __forceinline__ void gemm64(float* sA, float* sB, int kend, LA la, LB lb, ST st) {
    const int tid = threadIdx.x;
    const int tx = tid & 15, ty = tid >> 4;
    float acc[4][4];
#pragma unroll
    for (int i = 0; i < 4; i++)
#pragma unroll
        for (int j = 0; j < 4; j++) acc[i][j] = 0.f;
    for (int k0 = 0; k0 < kend; k0 += 32) {
#pragma unroll
        for (int i = 0; i < 8; i++) {
            int idx = tid + i * NT;
            int k = idx & 31, r = idx >> 5;
            sA[k * 68 + r] = la(r, k0 + k);
            sB[k * 68 + r] = lb(r, k0 + k);
        }
        __syncthreads();
#pragma unroll
        for (int kk = 0; kk < 32; kk++) {
            float4 a = *(const float4*)(sA + kk * 68 + 4 * ty);
            float4 b = *(const float4*)(sB + kk * 68 + 4 * tx);
            float av[4] = {a.x, a.y, a.z, a.w};
            float bv[4] = {b.x, b.y, b.z, b.w};
#pragma unroll
            for (int i = 0; i < 4; i++)
#pragma unroll
                for (int j = 0; j < 4; j++) acc[i][j] = fmaf(av[i], bv[j], acc[i][j]);
        }
        __syncthreads();
    }
#pragma unroll
    for (int i = 0; i < 4; i++)
        st(4 * ty + i, 4 * tx, make_float4(acc[i][0], acc[i][1], acc[i][2], acc[i][3]));
}

// stage one A big-chunk (K=128): 2 sub-slabs x 128 rows x 64 K-cols -> 32KB
__device__ __forceinline__ void stage_a(uint32_t ab, const __half* A, int kg) {
    const int tid = threadIdx.x;
#pragma unroll
    for (int it = 0; it < 8; it++) {
        int id = tid + it * NT;                      // 0..2047
        int sub = id >> 10, rem = id & 1023;
        int r = rem >> 3, seg = rem & 7;
        const __half* s = A + (size_t)r * HH + kg + sub * 64 + seg * 8;
        cp16(ab + sub * 16384 + r * 128 + ((seg ^ (r & 7)) << 4), s);
    }
    CP_COMMIT();
}

// K=128 big-chunk, job 128x64: 8 warps = 4M(32) x 2N(32), 2 products (a0b0, a0b1)
__device__ __forceinline__ void chunk_mma(float acc[2][4][4], uint32_t ab, uint32_t pb,
                                          int wm, int wn, int lane) {
#pragma unroll
    for (int sub = 0; sub < 2; sub++) {
        const uint32_t a0 = ab + sub * 16384;
        const uint32_t p0 = pb + sub * 16384;
#pragma unroll
        for (int kk = 0; kk < 4; kk++) {
            uint32_t af[2][4];
#pragma unroll
            for (int mt = 0; mt < 2; mt++) {
                int row = wm * 32 + mt * 16 + (lane & 15);
                int ch = kk * 2 + (lane >> 4);
                LDSM4(af[mt], a0 + row * 128 + ((ch ^ (row & 7)) << 4));
            }
            uint32_t bf[2][8];
#pragma unroll
            for (int j = 0; j < 2; j++)
#pragma unroll
                for (int q = 0; q < 2; q++) {
                    int nrow = wn * 32 + q * 16 + (lane & 7) + ((lane & 16) ? 8 : 0);
                    int ch = kk * 2 + ((lane >> 3) & 1);
                    LDSM4(&bf[j][q * 4], p0 + j * 8192 + nrow * 128 + ((ch ^ (nrow & 7)) << 4));
                }
#pragma unroll
            for (int j = 0; j < 2; j++)
#pragma unroll
                for (int mt = 0; mt < 2; mt++)
#pragma unroll
                    for (int nt = 0; nt < 4; nt++) {
                        int q = nt >> 1, o = (nt & 1) * 2;
                        MMA16816(acc[mt][nt], af[mt], bf[j][q * 4 + o], bf[j][q * 4 + o + 1]);
                    }
        }
    }
}

// tensor job: D[128,64] = h_q @ (W0+W1)^T over nch2 K=128 chunks, B persistent in smem
template <typename EPI>
__device__ __forceinline__ void mma_job(const __half* __restrict__ A,
                                        int kglob0, int nch2, uint32_t dyn, EPI epi) {
    const int tid = threadIdx.x;
    const int lane = tid & 31;
    const int warp = tid >> 5;
    const int wm = warp >> 1, wn = warp & 1;

    float acc[2][4][4];
#pragma unroll
    for (int a = 0; a < 2; a++)
#pragma unroll
        for (int b = 0; b < 4; b++)
#pragma unroll
            for (int c = 0; c < 4; c++) acc[a][b][c] = 0.f;

    stage_a(dyn + AB0, A, kglob0);
    if (nch2 > 1) stage_a(dyn + AB0 + ABSZ, A, kglob0 + 128);
    for (int c = 0; c < nch2; c++) {
        if (c + 1 < nch2) { CP_WAIT1(); } else { CP_WAIT0(); }
        __syncthreads();
        chunk_mma(acc, dyn + AB0 + (c & 1) * ABSZ, dyn + c * 32768, wm, wn, lane);
        __syncthreads();
        if (c + 2 < nch2) stage_a(dyn + AB0 + (c & 1) * ABSZ, A, kglob0 + (c + 2) * 128);
    }
#pragma unroll
    for (int mt = 0; mt < 2; mt++)
#pragma unroll
        for (int nt = 0; nt < 4; nt++) {
            int r = wm * 32 + mt * 16 + (lane >> 2);
            int cc = wn * 32 + nt * 8 + (lane & 3) * 2;
            epi(r, cc, acc[mt][nt][0], acc[mt][nt][1]);
            epi(r + 8, cc, acc[mt][nt][2], acc[mt][nt][3]);
        }
}

__global__ void __launch_bounds__(NT, 1) rnn_mma_kernel(
    const int*   __restrict__ ids,   const float* __restrict__ emb,
    const float* __restrict__ w_xh0, const float* __restrict__ w_hh0,
    const float* __restrict__ b_h0,  const float* __restrict__ w_xh1,
    const float* __restrict__ w_hh1, const float* __restrict__ b_h1,
    const float* __restrict__ w_hy,  const float* __restrict__ b_y,
    float* __restrict__ out, long long out_size)
{
    extern __shared__ __align__(16) char dynsm[];
    const int bid = blockIdx.x;
    const int tid = threadIdx.x;
    const uint32_t dyn = (smem_u32(dynsm) + 1023u) & ~1023u;
    const long long full = (long long)BTV + 2LL * BH;

    unsigned long long ep = g_ep[bid];

    // ---- fixed job assignment ----
    // role 0: bid 0..31   P0  = h0 @ w_hh0^T   (16 n x 2 kc, K=512, nch2=4)
    // role 1: bid 32..63  P1a = h0 @ w_xh1^T
    // role 2: bid 64..95  P1b = h1 @ w_hh1^T
    // role 3: bid 96..127 LOG = h1 @ w_hy^T    (8 n x 4 kc, K=256, nch2=2)
    int role, n0, kbeg, nsub, nch2, pstride;
    const __half *Bs0, *Bs1;
    float* pdst;
    if (bid < 32) {
        role = 0; n0 = (bid & 15) * 64; int kc = bid >> 4;
        kbeg = kc * 512; nsub = 8; nch2 = 4; Bs0 = g_w0sp[0]; Bs1 = g_w0sp[1];
        pdst = g_P0p[kc]; pstride = HH;
    } else if (bid < 64) {
        role = 1; int j = bid - 32; n0 = (j & 15) * 64; int kc = j >> 4;
        kbeg = kc * 512; nsub = 8; nch2 = 4; Bs0 = g_w1sp[0]; Bs1 = g_w1sp[1];
        pdst = g_P1p[kc]; pstride = HH;
    } else if (bid < 96) {
        role = 2; int j = bid - 64; n0 = (j & 15) * 64; int kc = j >> 4;
        kbeg = kc * 512; nsub = 8; nch2 = 4; Bs0 = g_w2sp[0]; Bs1 = g_w2sp[1];
        pdst = g_P1p[2 + kc]; pstride = HH;
    } else {
        role = 3; int j = bid - 96; n0 = (j >> 2) * 64; int kc = j & 3;
        kbeg = kc * 256; nsub = 4; nch2 = 2; Bs0 = g_wysp[0]; Bs1 = g_wysp[1];
        pdst = g_Py[kc]; pstride = VV;
    }

    // ============ prologue ============
    {
        const float* W[4] = {w_hh0, w_xh1, w_hh1, w_hy};
        __half* S0[4] = {g_w0sp[0], g_w1sp[0], g_w2sp[0], g_wysp[0]};
        __half* S1[4] = {g_w0sp[1], g_w1sp[1], g_w2sp[1], g_wysp[1]};
        const int SZ[4] = {HH * HH, HH * HH, HH * HH, VV * HH};
#pragma unroll
        for (int w = 0; w < 4; w++)
            for (int i = bid * NT + tid; i < SZ[w]; i += NB * NT)
                wsplit(W[w][i], S0[w][i], S1[w][i]);
        for (int i = bid * NT + tid; i < BH; i += NB * NT)     // h1_{-1} = 0
            g_h1h[i] = __float2half(0.f);
    }
    {   // tokproj[v][h] = b_h0[h] + emb[v] . w_xh0[h]
        float* sA = (float*)dynsm;
        float* sB = sA + 32 * 68;
        int m0 = (bid & 7) * 64, n0t = (bid >> 3) * 64;
        gemm64(sA, sB, EE,
            [&](int r, int k) { return emb[(m0 + r) * EE + k]; },
            [&](int r, int k) { return w_xh0[(n0t + r) * EE + k]; },
            [&](int m, int n, float4 v) {
                int col = n0t + n;
                float4 bb = *(const float4*)(b_h0 + col);
                v.x += bb.x; v.y += bb.y; v.z += bb.z; v.w += bb.w;
                *(float4*)(g_tokproj + (size_t)(m0 + m) * HH + col) = v;
            });
    }
    grid_bar(ep);

    // ---- persistent B slabs: nsub sub-slabs x (2 terms x 64 rows x 128B) ----
    {
        const int total = nsub * 1024;
        for (int x = tid; x < total; x += NT) {
            int c = x >> 10, rem = x & 1023;
            int jt = rem >> 9, r = (rem >> 3) & 63, seg = rem & 7;
            const __half* s = (jt ? Bs1 : Bs0)
                + (size_t)(n0 + r) * HH + kbeg + c * 64 + seg * 8;
            uint4 v = *(const uint4*)s;
            STS128(dyn + c * BCH + jt * 8192 + r * 128 + ((seg ^ (r & 7)) << 4),
                   v.x, v.y, v.z, v.w);
        }
        __syncthreads();
    }

    auto epi_part = [&](int r, int c, float v0, float v1) {
        *(float2*)(pdst + (size_t)r * pstride + n0 + c) = make_float2(v0, v1);
    };

    // ============ pipelined loop: t = 0 .. TT ============
    for (int t = 0; t <= TT; t++) {
        // ---- E phase (block = batch row bid) ----
        {
            if (t > 0) {                   // finalize h1_{t-1}
                const int i = tid * 4;
                const size_t idx = (size_t)bid * HH + i;
                float4 a = __ldcg((const float4*)&g_P1p[0][idx]);
                float4 b = __ldcg((const float4*)&g_P1p[1][idx]);
                float4 c = __ldcg((const float4*)&g_P1p[2][idx]);
                float4 d = __ldcg((const float4*)&g_P1p[3][idx]);
                float4 bb = *(const float4*)(b_h1 + i);
                float4 v;
                v.x = tanhf(bb.x + a.x + b.x + c.x + d.x);
                v.y = tanhf(bb.y + a.y + b.y + c.y + d.y);
                v.z = tanhf(bb.z + a.z + b.z + c.z + d.z);
                v.w = tanhf(bb.w + a.w + b.w + c.w + d.w);
                st_h4(g_h1h, idx, v);
                if (t == TT && out_size >= full)
                    *(float4*)&out[BTV + BH + idx] = v;              // final h1
            }
            if (t < TT) {                  // compute h0_t
                const int i = tid * 4;
                const size_t idx = (size_t)bid * HH + i;
                const int id_tok = ids[bid * TT + t];
                float4 s = *(const float4*)(g_tokproj + (size_t)id_tok * HH + i);
                if (t > 0) {
                    float4 a = __ldcg((const float4*)&g_P0p[0][idx]);
                    float4 b = __ldcg((const float4*)&g_P0p[1][idx]);
                    s.x += a.x + b.x; s.y += a.y + b.y;
                    s.z += a.z + b.z; s.w += a.w + b.w;
                }
                float4 v;
                v.x = tanhf(s.x); v.y = tanhf(s.y);
                v.z = tanhf(s.z); v.w = tanhf(s.w);
                st_h4(g_h0h, idx, v);
                if (t == TT - 1 && out_size >= full)
                    *(float4*)&out[BTV + idx] = v;                   // final h0
            }
            if (t >= 2) {                  // reduce logits for step t-2
                const int v0 = tid * 2;
                const size_t pidx = (size_t)bid * VV + v0;
                float2 r = *(const float2*)(b_y + v0);
#pragma unroll
                for (int k = 0; k < 4; k++) {
                    float2 p = __ldcg((const float2*)&g_Py[k][pidx]);
                    r.x += p.x; r.y += p.y;
                }
                *(float2*)&out[((size_t)bid * TT + (t - 2)) * VV + v0] = r;
            }
        }
        grid_bar(ep);

        // ---- G phase ----
        if (role == 0) {
            if (t < TT - 1) mma_job(g_h0h, kbeg, nch2, dyn, epi_part);
        } else if (role == 1) {
            if (t < TT)     mma_job(g_h0h, kbeg, nch2, dyn, epi_part);
        } else if (role == 2) {
            if (t < TT)     mma_job(g_h1h, kbeg, nch2, dyn, epi_part);
        } else {
            if (t >= 1)     mma_job(g_h1h, kbeg, nch2, dyn, epi_part);
        }
        grid_bar(ep);
    }

    // ============ post-loop: logits row TT-1 ============
    {
        const int v0 = tid * 2;
        const size_t pidx = (size_t)bid * VV + v0;
        float2 r = *(const float2*)(b_y + v0);
#pragma unroll
        for (int k = 0; k < 4; k++) {
            float2 p = __ldcg((const float2*)&g_Py[k][pidx]);
            r.x += p.x; r.y += p.y;
        }
        *(float2*)&out[((size_t)bid * TT + (TT - 1)) * VV + v0] = r;
    }
    if (tid == 0) g_ep[bid] = ep;
}

extern "C" void kernel_launch(void* const* d_in, const int* in_sizes, int n_in,
                              void* d_out, int out_size) {
    const int*   ids   = (const int*)d_in[0];
    const float* emb   = (const float*)d_in[1];
    const float* w_xh0 = (const float*)d_in[2];
    const float* w_hh0 = (const float*)d_in[3];
    const float* b_h0  = (const float*)d_in[4];
    const float* w_xh1 = (const float*)d_in[5];
    const float* w_hh1 = (const float*)d_in[6];
    const float* b_h1  = (const float*)d_in[7];
    const float* w_hy  = (const float*)d_in[8];
    const float* b_y   = (const float*)d_in[9];
    float* out = (float*)d_out;

    cudaFuncSetAttribute(rnn_mma_kernel, cudaFuncAttributeMaxDynamicSharedMemorySize,
                         DYNB_ALLOC);
    rnn_mma_kernel<<<NB, NT, DYNB_ALLOC>>>(ids, emb, w_xh0, w_hh0, b_h0,
                                           w_xh1, w_hh1, b_h1, w_hy, b_y,
                                           out, (long long)out_size);
}